// round 2
// baseline (speedup 1.0000x reference)
#include <cuda_runtime.h>
#include <math.h>

#define BB 256
#define NT 128
#define TD 64
#define HH 8
#define DH 64
#define IN 512
#define MM 266
#define FH 256

#define DN    0.35355339059327373f   /* 64^-0.25 */
#define RATIO 0.0613139076f          /* 266^-0.5 */
#define RE    6.13139076e-6f         /* RATIO * 1e-4 */

__device__ float g_q[BB*HH*NT*DH];
__device__ float g_k[BB*HH*NT*DH];
__device__ float g_v[BB*HH*NT*DH];
__device__ float g_ctxU[BB*HH*MM*DH];
__device__ float g_ksumU[BB*HH*MM];
__device__ float g_vsum[BB*HH*DH];
__device__ float g_o[BB*NT*IN];
__device__ float g_t[BB*NT*TD];
__device__ unsigned g_kmax;

__device__ __forceinline__ unsigned enc_f(float f) {
    unsigned u = __float_as_uint(f);
    return (u & 0x80000000u) ? ~u : (u | 0x80000000u);
}
__device__ __forceinline__ float dec_f(unsigned k) {
    return (k & 0x80000000u) ? __uint_as_float(k & 0x7fffffffu)
                             : __uint_as_float(~k);
}

__global__ void k_init() { g_kmax = 0u; }

// ---------------- K1: LN1 + QKV projection ----------------
__global__ __launch_bounds__(512, 1)
void k1_ln_qkv(const float* __restrict__ x,
               const float* __restrict__ g1, const float* __restrict__ b1,
               const float* __restrict__ Wq, const float* __restrict__ bq,
               const float* __restrict__ Wk, const float* __restrict__ bk,
               const float* __restrict__ Wv, const float* __restrict__ bv)
{
    __shared__ float hsm[NT*65];
    int b = blockIdx.x, tid = threadIdx.x;
    const float* xb = x + (size_t)b*NT*TD;
    for (int i = tid; i < NT*TD; i += 512)
        hsm[(i >> 6)*65 + (i & 63)] = xb[i];
    __syncthreads();
    if (tid < NT) {
        float* r = &hsm[tid*65];
        float mu = 0.f;
#pragma unroll
        for (int d = 0; d < 64; d++) mu += r[d];
        mu *= (1.f/64.f);
        float var = 0.f;
#pragma unroll
        for (int d = 0; d < 64; d++) { float t = r[d]-mu; var += t*t; }
        var *= (1.f/64.f);
        float inv = rsqrtf(var + 1e-5f);
#pragma unroll
        for (int d = 0; d < 64; d++) r[d] = (r[d]-mu)*inv*g1[d] + b1[d];
    }
    __syncthreads();

    int jt = tid & 127, ng = tid >> 7;
    int j4 = jt*4;
    int head = j4 >> 6, doff = j4 & 63;

#define PROJ_PASS(W, bias, dst_arr)                                         \
    {                                                                       \
        float4 bb4 = *(const float4*)((bias) + j4);                         \
        for (int it = 0; it < 32; ++it) {                                   \
            int n = it*4 + ng;                                              \
            float4 a = bb4;                                                 \
            _Pragma("unroll")                                               \
            for (int d = 0; d < 64; ++d) {                                  \
                float hv = hsm[n*65 + d];                                   \
                float4 w = *(const float4*)((W) + d*IN + j4);               \
                a.x = fmaf(hv, w.x, a.x); a.y = fmaf(hv, w.y, a.y);         \
                a.z = fmaf(hv, w.z, a.z); a.w = fmaf(hv, w.w, a.w);         \
            }                                                               \
            int dst = ((b*HH + head)*NT + n)*DH + doff;                     \
            *(float4*)((dst_arr) + dst) = a;                                \
        }                                                                   \
    }
    PROJ_PASS(Wq, bq, g_q)
    PROJ_PASS(Wk, bk, g_k)
    PROJ_PASS(Wv, bv, g_v)
#undef PROJ_PASS
}

// ---------------- K2: key features + ctxU/ksumU/vsum + global max ----------------
#define K2_THREADS 288
#define K2_SMEM ((NT*DH + NT*DH + NT)*4)

__global__ __launch_bounds__(K2_THREADS, 1)
void k2_keys(const float* __restrict__ proj)
{
    extern __shared__ float sm2[];
    float* ks   = sm2;            // k*dn  [128][64]
    float* vs   = ks + NT*DH;     // v     [128][64]
    float* diag = vs + NT*DH;     // [128]
    __shared__ unsigned s_max;

    int bh = blockIdx.x, tid = threadIdx.x;
    if (tid == 0) s_max = 0u;

    const float* kg = g_k + (size_t)bh*NT*DH;
    const float* vg = g_v + (size_t)bh*NT*DH;
    for (int i = tid; i < NT*DH; i += K2_THREADS) {
        ks[i] = kg[i] * DN;
        vs[i] = vg[i];
    }
    __syncthreads();
    if (tid < NT) {
        float s = 0.f;
#pragma unroll
        for (int d = 0; d < 64; d++) { float t = ks[tid*64 + d]; s += t*t; }
        diag[tid] = 0.5f * s;
    }
    __syncthreads();

    float dmax = -1e30f;
    if (tid < MM) {
        int m = tid;
        float pr[64];
#pragma unroll
        for (int j = 0; j < 16; ++j) {
            float4 p4 = *(const float4*)(proj + m*64 + 4*j);
            pr[4*j+0] = p4.x; pr[4*j+1] = p4.y; pr[4*j+2] = p4.z; pr[4*j+3] = p4.w;
        }
        float acc[64];
#pragma unroll
        for (int j = 0; j < 64; ++j) acc[j] = 0.f;
        float ksum = 0.f;

        for (int n = 0; n < NT; ++n) {
            float d0 = 0.f, d1 = 0.f, d2 = 0.f, d3 = 0.f;
#pragma unroll
            for (int j = 0; j < 16; ++j) {
                float4 kk = *(float4*)&ks[n*64 + 4*j];
                d0 = fmaf(kk.x, pr[4*j+0], d0);
                d1 = fmaf(kk.y, pr[4*j+1], d1);
                d2 = fmaf(kk.z, pr[4*j+2], d2);
                d3 = fmaf(kk.w, pr[4*j+3], d3);
            }
            float dd = (d0 + d1) + (d2 + d3);
            dmax = fmaxf(dmax, dd);
            float e = __expf(dd - diag[n]);
            ksum += e;
#pragma unroll
            for (int j = 0; j < 16; ++j) {
                float4 vv = *(float4*)&vs[n*64 + 4*j];
                acc[4*j+0] = fmaf(e, vv.x, acc[4*j+0]);
                acc[4*j+1] = fmaf(e, vv.y, acc[4*j+1]);
                acc[4*j+2] = fmaf(e, vv.z, acc[4*j+2]);
                acc[4*j+3] = fmaf(e, vv.w, acc[4*j+3]);
            }
        }
        float* dst = g_ctxU + ((size_t)bh*MM + m)*DH;
#pragma unroll
        for (int j = 0; j < 16; ++j)
            *(float4*)(dst + 4*j) =
                make_float4(acc[4*j+0], acc[4*j+1], acc[4*j+2], acc[4*j+3]);
        g_ksumU[(size_t)bh*MM + m] = ksum;
    }

    unsigned key = (tid < MM) ? enc_f(dmax) : 0u;
#pragma unroll
    for (int o = 16; o; o >>= 1)
        key = max(key, __shfl_xor_sync(0xffffffffu, key, o));
    if ((tid & 31) == 0) atomicMax(&s_max, key);
    __syncthreads();
    if (tid == 0) atomicMax(&g_kmax, s_max);

    if (tid < DH) {
        float s = 0.f;
        for (int n = 0; n < NT; ++n) s += vs[n*64 + tid];
        g_vsum[(size_t)bh*DH + tid] = s;
    }
}

// ---------------- K3: query features + linear attention output ----------------
#define K3_SMEM ((MM*64 + MM*64 + 268 + 64 + 64 + 8)*4)

__global__ __launch_bounds__(256, 1)
void k3_query(const float* __restrict__ proj)
{
    extern __shared__ float sm3[];
    float* ctx  = sm3;                 // [266][64] scaled ctx
    float* ps   = ctx + MM*64;         // [266][64] proj
    float* ksum = ps + MM*64;          // [266]
    float* vssm = ksum + 268;          // [64]
    float* csum = vssm + 64;           // [64]
    float* sc   = csum + 64;           // [0]=kssum
    __shared__ float s_A;

    int bh = blockIdx.x, tid = threadIdx.x;
    int n = tid >> 1, half = tid & 1, off = half*32;

    const float* qg = g_q + (size_t)bh*NT*DH + n*DH + off;
    float qr[32];
#pragma unroll
    for (int j = 0; j < 8; ++j) {
        float4 q4 = *(const float4*)(qg + 4*j);
        qr[4*j+0] = q4.x*DN; qr[4*j+1] = q4.y*DN;
        qr[4*j+2] = q4.z*DN; qr[4*j+3] = q4.w*DN;
    }
    float dp = 0.f;
#pragma unroll
    for (int j = 0; j < 32; ++j) dp = fmaf(qr[j], qr[j], dp);
    float diag = 0.5f*(dp + __shfl_xor_sync(0xffffffffu, dp, 1));

    if (tid == 0) s_A = RATIO * __expf(-dec_f(g_kmax));
    if (tid < DH) vssm[tid] = g_vsum[(size_t)bh*DH + tid];
    __syncthreads();
    float A = s_A;

    const float* cg = g_ctxU + (size_t)bh*MM*DH;
    for (int i = tid; i < MM*DH; i += 256) {
        ctx[i] = fmaf(A, cg[i], RE*vssm[i & 63]);
        ps[i]  = proj[i];
    }
    for (int i = tid; i < MM; i += 256)
        ksum[i] = fmaf(A, g_ksumU[(size_t)bh*MM + i], RE*128.f);
    __syncthreads();

    if (tid < DH) {
        float s = 0.f;
        for (int m = 0; m < MM; ++m) s += ctx[m*64 + tid];
        csum[tid] = s;
    }
    if (tid == 64) {
        float s = 0.f;
        for (int m = 0; m < MM; ++m) s += ksum[m];
        sc[0] = s;
    }
    __syncthreads();
    float kssum = sc[0];

    float P[32];
#pragma unroll
    for (int j = 0; j < 32; ++j) P[j] = 0.f;
    float T = 0.f, rmax = -1e30f;

    for (int m = 0; m < MM; ++m) {
        const float* prow = &ps[m*64 + off];
        float d0 = 0.f, d1 = 0.f, d2 = 0.f, d3 = 0.f;
#pragma unroll
        for (int j = 0; j < 8; ++j) {
            float4 pp = *(float4*)(prow + 4*j);
            d0 = fmaf(qr[4*j+0], pp.x, d0);
            d1 = fmaf(qr[4*j+1], pp.y, d1);
            d2 = fmaf(qr[4*j+2], pp.z, d2);
            d3 = fmaf(qr[4*j+3], pp.w, d3);
        }
        float pd = (d0 + d1) + (d2 + d3);
        float dd = pd + __shfl_xor_sync(0xffffffffu, pd, 1);
        rmax = fmaxf(rmax, dd);
        float e = __expf(dd);
        T = fmaf(e, ksum[m], T);
        const float* crow = &ctx[m*64 + off];
#pragma unroll
        for (int j = 0; j < 8; ++j) {
            float4 cc = *(float4*)(crow + 4*j);
            P[4*j+0] = fmaf(e, cc.x, P[4*j+0]);
            P[4*j+1] = fmaf(e, cc.y, P[4*j+1]);
            P[4*j+2] = fmaf(e, cc.z, P[4*j+2]);
            P[4*j+3] = fmaf(e, cc.w, P[4*j+3]);
        }
    }

    float rq  = RATIO * __expf(-diag - rmax);
    float inv = 1.0f / fmaf(rq, T, RE*kssum);

    int b = bh >> 3, h = bh & 7;
    float* og = g_o + ((size_t)(b*NT + n))*IN + h*DH + off;
#pragma unroll
    for (int j = 0; j < 8; ++j) {
        float4 o4;
        o4.x = fmaf(rq, P[4*j+0], RE*csum[off+4*j+0])*inv;
        o4.y = fmaf(rq, P[4*j+1], RE*csum[off+4*j+1])*inv;
        o4.z = fmaf(rq, P[4*j+2], RE*csum[off+4*j+2])*inv;
        o4.w = fmaf(rq, P[4*j+3], RE*csum[off+4*j+3])*inv;
        *(float4*)(og + 4*j) = o4;
    }
}

// ---------------- K4a: t = tokens + o @ Wo + bo ----------------
#define K4A_SMEM (IN*TD*4)

__global__ __launch_bounds__(256, 1)
void k4a_proj(const float* __restrict__ x,
              const float* __restrict__ Wo, const float* __restrict__ bo)
{
    extern __shared__ float wsm[];
    int b = blockIdx.x, tid = threadIdx.x;
    for (int i = tid; i < IN*TD; i += 256) wsm[i] = Wo[i];
    __syncthreads();

    int jt = tid & 15, ng = tid >> 4;
    int j4 = jt*4;
    float4 b4 = *(const float4*)(bo + j4);
    for (int n = ng; n < NT; n += 16) {
        float4 a = b4;
        const float* orow = g_o + ((size_t)(b*NT + n))*IN;
        for (int i = 0; i < IN; i += 4) {
            float4 ov = *(const float4*)(orow + i);
            float4 w0 = *(float4*)&wsm[(i+0)*64 + j4];
            float4 w1 = *(float4*)&wsm[(i+1)*64 + j4];
            float4 w2 = *(float4*)&wsm[(i+2)*64 + j4];
            float4 w3 = *(float4*)&wsm[(i+3)*64 + j4];
            a.x = fmaf(ov.x, w0.x, a.x); a.y = fmaf(ov.x, w0.y, a.y);
            a.z = fmaf(ov.x, w0.z, a.z); a.w = fmaf(ov.x, w0.w, a.w);
            a.x = fmaf(ov.y, w1.x, a.x); a.y = fmaf(ov.y, w1.y, a.y);
            a.z = fmaf(ov.y, w1.z, a.z); a.w = fmaf(ov.y, w1.w, a.w);
            a.x = fmaf(ov.z, w2.x, a.x); a.y = fmaf(ov.z, w2.y, a.y);
            a.z = fmaf(ov.z, w2.z, a.z); a.w = fmaf(ov.z, w2.w, a.w);
            a.x = fmaf(ov.w, w3.x, a.x); a.y = fmaf(ov.w, w3.y, a.y);
            a.z = fmaf(ov.w, w3.z, a.z); a.w = fmaf(ov.w, w3.w, a.w);
        }
        const float* xr = x + (size_t)b*NT*TD + n*TD + j4;
        float4 x4 = *(const float4*)xr;
        *(float4*)(g_t + (size_t)b*NT*TD + n*TD + j4) =
            make_float4(a.x + x4.x, a.y + x4.y, a.z + x4.z, a.w + x4.w);
    }
}

// ---------------- K4b: LN2 + FF(GELU) + LN3 + pool + head ----------------
#define K4B_SMEM ((NT*65 + NT*FH + TD*FH + 64 + 16)*4)

__global__ __launch_bounds__(256, 1)
void k4b_ff_head(const float* __restrict__ x,
                 const float* __restrict__ g2, const float* __restrict__ b2,
                 const float* __restrict__ W1, const float* __restrict__ c1,
                 const float* __restrict__ W2, const float* __restrict__ c2,
                 const float* __restrict__ g3, const float* __restrict__ b3,
                 const float* __restrict__ Wf1, const float* __restrict__ bf1,
                 const float* __restrict__ Wf2, const float* __restrict__ bf2,
                 float* __restrict__ out)
{
    extern __shared__ float sm4[];
    float* h2  = sm4;               // [128][65]
    float* gsm = h2 + NT*65;        // [128][256]
    float* wsm = gsm + NT*FH;       // [64*256] W1, then W2
    float* psm = wsm + TD*FH;       // [64]
    float* red = psm + 64;          // [16]

    int b = blockIdx.x, tid = threadIdx.x;

    if (tid < NT) {
        const float* tr = g_t + ((size_t)(b*NT + tid))*TD;
        float tv[64];
#pragma unroll
        for (int j = 0; j < 16; ++j) {
            float4 t4 = *(const float4*)(tr + 4*j);
            tv[4*j+0]=t4.x; tv[4*j+1]=t4.y; tv[4*j+2]=t4.z; tv[4*j+3]=t4.w;
        }
        float mu = 0.f;
#pragma unroll
        for (int d = 0; d < 64; d++) mu += tv[d];
        mu *= (1.f/64.f);
        float var = 0.f;
#pragma unroll
        for (int d = 0; d < 64; d++) { float t = tv[d]-mu; var += t*t; }
        var *= (1.f/64.f);
        float inv = rsqrtf(var + 1e-5f);
#pragma unroll
        for (int d = 0; d < 64; d++)
            h2[tid*65 + d] = (tv[d]-mu)*inv*g2[d] + b2[d];
    }
    for (int i = tid; i < TD*FH; i += 256) wsm[i] = W1[i];
    __syncthreads();

    {   // gsm = gelu(h2 @ W1 + c1)
        int pt = tid & 63, grp = tid >> 6;
        int p4 = pt*4;
        float4 c14 = *(const float4*)(c1 + p4);
        for (int n = grp; n < NT; n += 4) {
            float4 a = c14;
#pragma unroll
            for (int j = 0; j < TD; ++j) {
                float hv = h2[n*65 + j];
                float4 w = *(float4*)&wsm[j*FH + p4];
                a.x = fmaf(hv, w.x, a.x); a.y = fmaf(hv, w.y, a.y);
                a.z = fmaf(hv, w.z, a.z); a.w = fmaf(hv, w.w, a.w);
            }
            a.x = 0.5f*a.x*(1.f + erff(a.x*0.70710678f));
            a.y = 0.5f*a.y*(1.f + erff(a.y*0.70710678f));
            a.z = 0.5f*a.z*(1.f + erff(a.z*0.70710678f));
            a.w = 0.5f*a.w*(1.f + erff(a.w*0.70710678f));
            *(float4*)&gsm[n*FH + p4] = a;
        }
    }
    __syncthreads();
    for (int i = tid; i < FH*TD; i += 256) wsm[i] = W2[i];
    __syncthreads();

    {   // r = t + gsm@W2 + c2 + tokens -> h2
        int jt = tid & 15, grp = tid >> 4;
        int j4 = jt*4;
        float4 c24 = *(const float4*)(c2 + j4);
        for (int n = grp; n < NT; n += 16) {
            float4 a = c24;
            for (int p = 0; p < FH; ++p) {
                float gv = gsm[n*FH + p];
                float4 w = *(float4*)&wsm[p*64 + j4];
                a.x = fmaf(gv, w.x, a.x); a.y = fmaf(gv, w.y, a.y);
                a.z = fmaf(gv, w.z, a.z); a.w = fmaf(gv, w.w, a.w);
            }
            float4 t4 = *(const float4*)(g_t + (size_t)b*NT*TD + n*TD + j4);
            float4 x4 = *(const float4*)(x   + (size_t)b*NT*TD + n*TD + j4);
            h2[n*65 + j4 + 0] = a.x + t4.x + x4.x;
            h2[n*65 + j4 + 1] = a.y + t4.y + x4.y;
            h2[n*65 + j4 + 2] = a.z + t4.z + x4.z;
            h2[n*65 + j4 + 3] = a.w + t4.w + x4.w;
        }
    }
    __syncthreads();

    if (tid < NT) {   // LN3
        float* r = &h2[tid*65];
        float mu = 0.f;
#pragma unroll
        for (int d = 0; d < 64; d++) mu += r[d];
        mu *= (1.f/64.f);
        float var = 0.f;
#pragma unroll
        for (int d = 0; d < 64; d++) { float t = r[d]-mu; var += t*t; }
        var *= (1.f/64.f);
        float inv = rsqrtf(var + 1e-5f);
#pragma unroll
        for (int d = 0; d < 64; d++)
            r[d] = (r[d]-mu)*inv*g3[d] + b3[d];
    }
    __syncthreads();

    if (tid < TD) {   // mean pool
        float s = 0.f;
        for (int n = 0; n < NT; ++n) s += h2[n*65 + tid];
        psm[tid] = s * (1.f/128.f);
    }
    __syncthreads();

    float val = 0.f;
    if (tid < 128) {  // head MLP
        float s = bf1[tid];
        for (int d = 0; d < TD; ++d)
            s = fmaf(psm[d], Wf1[d*128 + tid], s);
        s = fmaxf(s, 0.f);
        val = s * Wf2[tid];
    }
#pragma unroll
    for (int o = 16; o; o >>= 1)
        val += __shfl_xor_sync(0xffffffffu, val, o);
    if ((tid & 31) == 0) red[tid >> 5] = val;
    __syncthreads();
    if (tid == 0)
        out[b] = red[0] + red[1] + red[2] + red[3] + bf2[0];
}

// ---------------- launch ----------------
extern "C" void kernel_launch(void* const* d_in, const int* in_sizes, int n_in,
                              void* d_out, int out_size) {
    const float* x    = (const float*)d_in[0];
    const float* g1   = (const float*)d_in[1];
    const float* b1   = (const float*)d_in[2];
    const float* Wq   = (const float*)d_in[3];
    const float* bq   = (const float*)d_in[4];
    const float* Wk   = (const float*)d_in[5];
    const float* bk   = (const float*)d_in[6];
    const float* Wv   = (const float*)d_in[7];
    const float* bv   = (const float*)d_in[8];
    const float* Wo   = (const float*)d_in[9];
    const float* bo   = (const float*)d_in[10];
    const float* proj = (const float*)d_in[11];
    const float* g2   = (const float*)d_in[12];
    const float* b2   = (const float*)d_in[13];
    const float* W1   = (const float*)d_in[14];
    const float* c1   = (const float*)d_in[15];
    const float* W2   = (const float*)d_in[16];
    const float* c2   = (const float*)d_in[17];
    const float* g3   = (const float*)d_in[18];
    const float* b3   = (const float*)d_in[19];
    const float* Wf1  = (const float*)d_in[20];
    const float* bf1  = (const float*)d_in[21];
    const float* Wf2  = (const float*)d_in[22];
    const float* bf2  = (const float*)d_in[23];
    float* out = (float*)d_out;

    cudaFuncSetAttribute(k2_keys,    cudaFuncAttributeMaxDynamicSharedMemorySize, K2_SMEM);
    cudaFuncSetAttribute(k3_query,   cudaFuncAttributeMaxDynamicSharedMemorySize, K3_SMEM);
    cudaFuncSetAttribute(k4a_proj,   cudaFuncAttributeMaxDynamicSharedMemorySize, K4A_SMEM);
    cudaFuncSetAttribute(k4b_ff_head,cudaFuncAttributeMaxDynamicSharedMemorySize, K4B_SMEM);

    k_init<<<1, 1>>>();
    k1_ln_qkv<<<BB, 512>>>(x, g1, b1, Wq, bq, Wk, bk, Wv, bv);
    k2_keys<<<BB*HH, K2_THREADS, K2_SMEM>>>(proj);
    k3_query<<<BB*HH, 256, K3_SMEM>>>(proj);
    k4a_proj<<<BB, 256, K4A_SMEM>>>(x, Wo, bo);
    k4b_ff_head<<<BB, 256, K4B_SMEM>>>(x, g2, b2, W1, c1, W2, c2,
                                       g3, b3, Wf1, bf1, Wf2, bf2, out);
}

// round 3
// speedup vs baseline: 1.0864x; 1.0864x over previous
#include <cuda_runtime.h>
#include <math.h>

#define BB 256
#define NT 128
#define TD 64
#define HH 8
#define DH 64
#define IN 512
#define MM 266
#define FH 256

#define DN    0.35355339059327373f   /* 64^-0.25 */
#define RATIO 0.0613139076f          /* 266^-0.5 */
#define RE    6.13139076e-6f         /* RATIO * 1e-4 */

__device__ float g_q[BB*HH*NT*DH];
__device__ float g_k[BB*HH*NT*DH];
__device__ float g_v[BB*HH*NT*DH];
__device__ float g_ctxU[BB*HH*MM*DH];
__device__ float g_ksumU[BB*HH*MM];
__device__ float g_vsum[BB*HH*DH];
__device__ float g_o[BB*NT*IN];
__device__ float g_t[BB*NT*TD];
__device__ unsigned g_kmax;

__device__ __forceinline__ unsigned enc_f(float f) {
    unsigned u = __float_as_uint(f);
    return (u & 0x80000000u) ? ~u : (u | 0x80000000u);
}
__device__ __forceinline__ float dec_f(unsigned k) {
    return (k & 0x80000000u) ? __uint_as_float(k & 0x7fffffffu)
                             : __uint_as_float(~k);
}

__global__ void k_init() { g_kmax = 0u; }

// ---------------- K1: LN1 + QKV projection ----------------
__global__ __launch_bounds__(512, 1)
void k1_ln_qkv(const float* __restrict__ x,
               const float* __restrict__ g1, const float* __restrict__ b1,
               const float* __restrict__ Wq, const float* __restrict__ bq,
               const float* __restrict__ Wk, const float* __restrict__ bk,
               const float* __restrict__ Wv, const float* __restrict__ bv)
{
    __shared__ float hsm[NT*65];
    int b = blockIdx.x, tid = threadIdx.x;
    const float* xb = x + (size_t)b*NT*TD;
    for (int i = tid; i < NT*TD; i += 512)
        hsm[(i >> 6)*65 + (i & 63)] = xb[i];
    __syncthreads();
    if (tid < NT) {
        float* r = &hsm[tid*65];
        float mu = 0.f;
#pragma unroll
        for (int d = 0; d < 64; d++) mu += r[d];
        mu *= (1.f/64.f);
        float var = 0.f;
#pragma unroll
        for (int d = 0; d < 64; d++) { float t = r[d]-mu; var += t*t; }
        var *= (1.f/64.f);
        float inv = rsqrtf(var + 1e-5f);
#pragma unroll
        for (int d = 0; d < 64; d++) r[d] = (r[d]-mu)*inv*g1[d] + b1[d];
    }
    __syncthreads();

    int jt = tid & 127, ng = tid >> 7;
    int j4 = jt*4;
    int head = j4 >> 6, doff = j4 & 63;

#define PROJ_PASS(W, bias, dst_arr)                                         \
    {                                                                       \
        float4 bb4 = *(const float4*)((bias) + j4);                         \
        for (int it = 0; it < 32; ++it) {                                   \
            int n = it*4 + ng;                                              \
            float4 a = bb4;                                                 \
            _Pragma("unroll")                                               \
            for (int d = 0; d < 64; ++d) {                                  \
                float hv = hsm[n*65 + d];                                   \
                float4 w = *(const float4*)((W) + d*IN + j4);               \
                a.x = fmaf(hv, w.x, a.x); a.y = fmaf(hv, w.y, a.y);         \
                a.z = fmaf(hv, w.z, a.z); a.w = fmaf(hv, w.w, a.w);         \
            }                                                               \
            int dst = ((b*HH + head)*NT + n)*DH + doff;                     \
            *(float4*)((dst_arr) + dst) = a;                                \
        }                                                                   \
    }
    PROJ_PASS(Wq, bq, g_q)
    PROJ_PASS(Wk, bk, g_k)
    PROJ_PASS(Wv, bv, g_v)
#undef PROJ_PASS
}

// ---------------- K2: key features + ctxU/ksumU/vsum + global max ----------------
#define K2_THREADS 288
#define K2_SMEM ((NT*DH + NT*DH + NT)*4)

__global__ __launch_bounds__(K2_THREADS, 1)
void k2_keys(const float* __restrict__ proj)
{
    extern __shared__ float sm2[];
    float* ks   = sm2;            // k*dn  [128][64]
    float* vs   = ks + NT*DH;     // v     [128][64]
    float* diag = vs + NT*DH;     // [128]
    __shared__ unsigned s_max;

    int bh = blockIdx.x, tid = threadIdx.x;
    if (tid == 0) s_max = 0u;

    const float* kg = g_k + (size_t)bh*NT*DH;
    const float* vg = g_v + (size_t)bh*NT*DH;
    for (int i = tid; i < NT*DH; i += K2_THREADS) {
        ks[i] = kg[i] * DN;
        vs[i] = vg[i];
    }
    __syncthreads();
    if (tid < NT) {
        float s = 0.f;
#pragma unroll
        for (int d = 0; d < 64; d++) { float t = ks[tid*64 + d]; s += t*t; }
        diag[tid] = 0.5f * s;
    }
    __syncthreads();

    float dmax = -1e30f;
    if (tid < MM) {
        int m = tid;
        float pr[64];
#pragma unroll
        for (int j = 0; j < 16; ++j) {
            float4 p4 = *(const float4*)(proj + m*64 + 4*j);
            pr[4*j+0] = p4.x; pr[4*j+1] = p4.y; pr[4*j+2] = p4.z; pr[4*j+3] = p4.w;
        }
        float acc[64];
#pragma unroll
        for (int j = 0; j < 64; ++j) acc[j] = 0.f;
        float ksum = 0.f;

        for (int n = 0; n < NT; ++n) {
            float d0 = 0.f, d1 = 0.f, d2 = 0.f, d3 = 0.f;
#pragma unroll
            for (int j = 0; j < 16; ++j) {
                float4 kk = *(float4*)&ks[n*64 + 4*j];
                d0 = fmaf(kk.x, pr[4*j+0], d0);
                d1 = fmaf(kk.y, pr[4*j+1], d1);
                d2 = fmaf(kk.z, pr[4*j+2], d2);
                d3 = fmaf(kk.w, pr[4*j+3], d3);
            }
            float dd = (d0 + d1) + (d2 + d3);
            dmax = fmaxf(dmax, dd);
            float e = __expf(dd - diag[n]);
            ksum += e;
#pragma unroll
            for (int j = 0; j < 16; ++j) {
                float4 vv = *(float4*)&vs[n*64 + 4*j];
                acc[4*j+0] = fmaf(e, vv.x, acc[4*j+0]);
                acc[4*j+1] = fmaf(e, vv.y, acc[4*j+1]);
                acc[4*j+2] = fmaf(e, vv.z, acc[4*j+2]);
                acc[4*j+3] = fmaf(e, vv.w, acc[4*j+3]);
            }
        }
        float* dst = g_ctxU + ((size_t)bh*MM + m)*DH;
#pragma unroll
        for (int j = 0; j < 16; ++j)
            *(float4*)(dst + 4*j) =
                make_float4(acc[4*j+0], acc[4*j+1], acc[4*j+2], acc[4*j+3]);
        g_ksumU[(size_t)bh*MM + m] = ksum;
    }

    unsigned key = (tid < MM) ? enc_f(dmax) : 0u;
#pragma unroll
    for (int o = 16; o; o >>= 1)
        key = max(key, __shfl_xor_sync(0xffffffffu, key, o));
    if ((tid & 31) == 0) atomicMax(&s_max, key);
    __syncthreads();
    if (tid == 0) atomicMax(&g_kmax, s_max);

    if (tid < DH) {
        float s = 0.f;
        for (int n = 0; n < NT; ++n) s += vs[n*64 + tid];
        g_vsum[(size_t)bh*DH + tid] = s;
    }
}

// ---------------- K3 v2: two-phase, FMA-bound ----------------
#define E_ST   269                         /* odd stride: conflict-free col reads */
#define CTX_ST 68
#define K3_SMEM ((NT*E_ST + MM*CTX_ST)*4)  /* E + union(qs,ctx) = 210,080 B */

__global__ __launch_bounds__(288, 1)
void k3_query(const float* __restrict__ proj)
{
    extern __shared__ float dsm[];
    float* E   = dsm;                 // [128][269]
    float* uni = dsm + NT*E_ST;       // qs [128][64]  then  ctx [266][68]
    __shared__ float diag[NT], ksum[MM], vs_s[DH], csum[DH], Tn[NT], Emx[NT];
    __shared__ float sA, skssum;

    int bh = blockIdx.x, t = threadIdx.x;

    // ---- fill qs (scaled), sA, vs_s; proj row into registers ----
    float* qs = uni;
    const float* qg = g_q + (size_t)bh*NT*DH;
    for (int i = t; i < NT*DH; i += 288) qs[i] = qg[i] * DN;
    if (t == 0) sA = RATIO * __expf(-dec_f(g_kmax));
    if (t < DH) vs_s[t] = g_vsum[(size_t)bh*DH + t];

    float pr[64];
    if (t < MM) {
#pragma unroll
        for (int j = 0; j < 16; ++j) {
            float4 p4 = *(const float4*)(proj + t*64 + 4*j);
            pr[4*j+0] = p4.x; pr[4*j+1] = p4.y; pr[4*j+2] = p4.z; pr[4*j+3] = p4.w;
        }
    }
    __syncthreads();

    // ---- diag from qs (t<128) ----
    if (t < NT) {
        float s = 0.f;
#pragma unroll
        for (int j = 0; j < 16; ++j) {
            float4 q4 = *(const float4*)&qs[t*64 + 4*j];
            s = fmaf(q4.x, q4.x, s); s = fmaf(q4.y, q4.y, s);
            s = fmaf(q4.z, q4.z, s); s = fmaf(q4.w, q4.w, s);
        }
        diag[t] = 0.5f * s;
    }

    // ---- Phase A: E[n][m] = exp(q_n . proj_m), thread=m ----
    if (t < MM) {
        for (int n = 0; n < NT; ++n) {
            float d0 = 0.f, d1 = 0.f, d2 = 0.f, d3 = 0.f;
#pragma unroll
            for (int j = 0; j < 16; ++j) {
                float4 qq = *(float4*)&qs[n*64 + 4*j];
                d0 = fmaf(qq.x, pr[4*j+0], d0);
                d1 = fmaf(qq.y, pr[4*j+1], d1);
                d2 = fmaf(qq.z, pr[4*j+2], d2);
                d3 = fmaf(qq.w, pr[4*j+3], d3);
            }
            E[n*E_ST + t] = __expf((d0 + d1) + (d2 + d3));
        }
    }
    __syncthreads();

    // ---- fill ctx (overwrites qs) + ksum ----
    float* ctx = uni;
    const float* cg = g_ctxU + (size_t)bh*MM*DH;
    float A = sA;
    for (int i = t; i < MM*DH; i += 288) {
        int m = i >> 6, d = i & 63;
        ctx[m*CTX_ST + d] = fmaf(A, cg[i], RE*vs_s[d]);
    }
    for (int i = t; i < MM; i += 288)
        ksum[i] = fmaf(A, g_ksumU[(size_t)bh*MM + i], RE*128.f);
    __syncthreads();

    // ---- pass X: csum | kssum | Tn,Emx (disjoint thread groups) ----
    if (t < DH) {
        float s = 0.f;
        for (int m = 0; m < MM; ++m) s += ctx[m*CTX_ST + t];
        csum[t] = s;
    } else if (t < 96) {
        int l = t - 64;
        float s = 0.f;
        for (int i = l; i < MM; i += 32) s += ksum[i];
#pragma unroll
        for (int o = 16; o; o >>= 1)
            s += __shfl_xor_sync(0xffffffffu, s, o);
        if (l == 0) skssum = s;
    } else if (t < 96 + NT) {
        int n = t - 96;
        float s = 0.f, mx = 0.f;
        const float* er = E + n*E_ST;
        for (int m = 0; m < MM; ++m) {
            float e = er[m];
            s  = fmaf(e, ksum[m], s);
            mx = fmaxf(mx, e);
        }
        Tn[n] = s; Emx[n] = mx;
    }
    __syncthreads();

    // ---- Phase B: O[128][64] = E @ ctx, 4n x 8d register tile ----
    if (t < 256) {
        int ng = t >> 3, dg = t & 7;
        int n0 = ng*4, d0 = dg*8;
        const float* e0p = E + (n0+0)*E_ST;
        const float* e1p = E + (n0+1)*E_ST;
        const float* e2p = E + (n0+2)*E_ST;
        const float* e3p = E + (n0+3)*E_ST;
        float acc[32];
#pragma unroll
        for (int j = 0; j < 32; ++j) acc[j] = 0.f;

        const float* cp = ctx + d0;
#pragma unroll 2
        for (int m = 0; m < MM; ++m) {
            float e0 = e0p[m], e1 = e1p[m], e2 = e2p[m], e3 = e3p[m];
            float4 c0 = *(const float4*)(cp);
            float4 c1 = *(const float4*)(cp + 4);
            cp += CTX_ST;
            acc[ 0]=fmaf(e0,c0.x,acc[ 0]); acc[ 1]=fmaf(e0,c0.y,acc[ 1]);
            acc[ 2]=fmaf(e0,c0.z,acc[ 2]); acc[ 3]=fmaf(e0,c0.w,acc[ 3]);
            acc[ 4]=fmaf(e0,c1.x,acc[ 4]); acc[ 5]=fmaf(e0,c1.y,acc[ 5]);
            acc[ 6]=fmaf(e0,c1.z,acc[ 6]); acc[ 7]=fmaf(e0,c1.w,acc[ 7]);
            acc[ 8]=fmaf(e1,c0.x,acc[ 8]); acc[ 9]=fmaf(e1,c0.y,acc[ 9]);
            acc[10]=fmaf(e1,c0.z,acc[10]); acc[11]=fmaf(e1,c0.w,acc[11]);
            acc[12]=fmaf(e1,c1.x,acc[12]); acc[13]=fmaf(e1,c1.y,acc[13]);
            acc[14]=fmaf(e1,c1.z,acc[14]); acc[15]=fmaf(e1,c1.w,acc[15]);
            acc[16]=fmaf(e2,c0.x,acc[16]); acc[17]=fmaf(e2,c0.y,acc[17]);
            acc[18]=fmaf(e2,c0.z,acc[18]); acc[19]=fmaf(e2,c0.w,acc[19]);
            acc[20]=fmaf(e2,c1.x,acc[20]); acc[21]=fmaf(e2,c1.y,acc[21]);
            acc[22]=fmaf(e2,c1.z,acc[22]); acc[23]=fmaf(e2,c1.w,acc[23]);
            acc[24]=fmaf(e3,c0.x,acc[24]); acc[25]=fmaf(e3,c0.y,acc[25]);
            acc[26]=fmaf(e3,c0.z,acc[26]); acc[27]=fmaf(e3,c0.w,acc[27]);
            acc[28]=fmaf(e3,c1.x,acc[28]); acc[29]=fmaf(e3,c1.y,acc[29]);
            acc[30]=fmaf(e3,c1.z,acc[30]); acc[31]=fmaf(e3,c1.w,acc[31]);
        }

        // ---- write: o = (rq*P + RE*csum) / (rq*T + RE*kssum) ----
        int b = bh >> 3, h = bh & 7;
        float kss = skssum;
#pragma unroll
        for (int i = 0; i < 4; ++i) {
            int n = n0 + i;
            float rq  = RATIO * __expf(-diag[n]) / Emx[n];
            float inv = 1.0f / fmaf(rq, Tn[n], RE*kss);
            float* og = g_o + ((size_t)(b*NT + n))*IN + h*DH + d0;
            float4 o0, o1;
            o0.x = fmaf(rq, acc[i*8+0], RE*csum[d0+0])*inv;
            o0.y = fmaf(rq, acc[i*8+1], RE*csum[d0+1])*inv;
            o0.z = fmaf(rq, acc[i*8+2], RE*csum[d0+2])*inv;
            o0.w = fmaf(rq, acc[i*8+3], RE*csum[d0+3])*inv;
            o1.x = fmaf(rq, acc[i*8+4], RE*csum[d0+4])*inv;
            o1.y = fmaf(rq, acc[i*8+5], RE*csum[d0+5])*inv;
            o1.z = fmaf(rq, acc[i*8+6], RE*csum[d0+6])*inv;
            o1.w = fmaf(rq, acc[i*8+7], RE*csum[d0+7])*inv;
            *(float4*)(og)     = o0;
            *(float4*)(og + 4) = o1;
        }
    }
}

// ---------------- K4a: t = tokens + o @ Wo + bo ----------------
#define K4A_SMEM (IN*TD*4)

__global__ __launch_bounds__(256, 1)
void k4a_proj(const float* __restrict__ x,
              const float* __restrict__ Wo, const float* __restrict__ bo)
{
    extern __shared__ float wsm[];
    int b = blockIdx.x, tid = threadIdx.x;
    for (int i = tid; i < IN*TD; i += 256) wsm[i] = Wo[i];
    __syncthreads();

    int jt = tid & 15, ng = tid >> 4;
    int j4 = jt*4;
    float4 b4 = *(const float4*)(bo + j4);
    for (int n = ng; n < NT; n += 16) {
        float4 a = b4;
        const float* orow = g_o + ((size_t)(b*NT + n))*IN;
        for (int i = 0; i < IN; i += 4) {
            float4 ov = *(const float4*)(orow + i);
            float4 w0 = *(float4*)&wsm[(i+0)*64 + j4];
            float4 w1 = *(float4*)&wsm[(i+1)*64 + j4];
            float4 w2 = *(float4*)&wsm[(i+2)*64 + j4];
            float4 w3 = *(float4*)&wsm[(i+3)*64 + j4];
            a.x = fmaf(ov.x, w0.x, a.x); a.y = fmaf(ov.x, w0.y, a.y);
            a.z = fmaf(ov.x, w0.z, a.z); a.w = fmaf(ov.x, w0.w, a.w);
            a.x = fmaf(ov.y, w1.x, a.x); a.y = fmaf(ov.y, w1.y, a.y);
            a.z = fmaf(ov.y, w1.z, a.z); a.w = fmaf(ov.y, w1.w, a.w);
            a.x = fmaf(ov.z, w2.x, a.x); a.y = fmaf(ov.z, w2.y, a.y);
            a.z = fmaf(ov.z, w2.z, a.z); a.w = fmaf(ov.z, w2.w, a.w);
            a.x = fmaf(ov.w, w3.x, a.x); a.y = fmaf(ov.w, w3.y, a.y);
            a.z = fmaf(ov.w, w3.z, a.z); a.w = fmaf(ov.w, w3.w, a.w);
        }
        const float* xr = x + (size_t)b*NT*TD + n*TD + j4;
        float4 x4 = *(const float4*)xr;
        *(float4*)(g_t + (size_t)b*NT*TD + n*TD + j4) =
            make_float4(a.x + x4.x, a.y + x4.y, a.z + x4.z, a.w + x4.w);
    }
}

// ---------------- K4b: LN2 + FF(GELU) + LN3 + pool + head ----------------
#define K4B_SMEM ((NT*65 + NT*FH + TD*FH + 64 + 16)*4)

__global__ __launch_bounds__(256, 1)
void k4b_ff_head(const float* __restrict__ x,
                 const float* __restrict__ g2, const float* __restrict__ b2,
                 const float* __restrict__ W1, const float* __restrict__ c1,
                 const float* __restrict__ W2, const float* __restrict__ c2,
                 const float* __restrict__ g3, const float* __restrict__ b3,
                 const float* __restrict__ Wf1, const float* __restrict__ bf1,
                 const float* __restrict__ Wf2, const float* __restrict__ bf2,
                 float* __restrict__ out)
{
    extern __shared__ float sm4[];
    float* h2  = sm4;               // [128][65]
    float* gsm = h2 + NT*65;        // [128][256]
    float* wsm = gsm + NT*FH;       // [64*256] W1, then W2
    float* psm = wsm + TD*FH;       // [64]
    float* red = psm + 64;          // [16]

    int b = blockIdx.x, tid = threadIdx.x;

    if (tid < NT) {
        const float* tr = g_t + ((size_t)(b*NT + tid))*TD;
        float tv[64];
#pragma unroll
        for (int j = 0; j < 16; ++j) {
            float4 t4 = *(const float4*)(tr + 4*j);
            tv[4*j+0]=t4.x; tv[4*j+1]=t4.y; tv[4*j+2]=t4.z; tv[4*j+3]=t4.w;
        }
        float mu = 0.f;
#pragma unroll
        for (int d = 0; d < 64; d++) mu += tv[d];
        mu *= (1.f/64.f);
        float var = 0.f;
#pragma unroll
        for (int d = 0; d < 64; d++) { float t = tv[d]-mu; var += t*t; }
        var *= (1.f/64.f);
        float inv = rsqrtf(var + 1e-5f);
#pragma unroll
        for (int d = 0; d < 64; d++)
            h2[tid*65 + d] = (tv[d]-mu)*inv*g2[d] + b2[d];
    }
    for (int i = tid; i < TD*FH; i += 256) wsm[i] = W1[i];
    __syncthreads();

    {   // gsm = gelu(h2 @ W1 + c1)
        int pt = tid & 63, grp = tid >> 6;
        int p4 = pt*4;
        float4 c14 = *(const float4*)(c1 + p4);
        for (int n = grp; n < NT; n += 4) {
            float4 a = c14;
#pragma unroll
            for (int j = 0; j < TD; ++j) {
                float hv = h2[n*65 + j];
                float4 w = *(float4*)&wsm[j*FH + p4];
                a.x = fmaf(hv, w.x, a.x); a.y = fmaf(hv, w.y, a.y);
                a.z = fmaf(hv, w.z, a.z); a.w = fmaf(hv, w.w, a.w);
            }
            a.x = 0.5f*a.x*(1.f + erff(a.x*0.70710678f));
            a.y = 0.5f*a.y*(1.f + erff(a.y*0.70710678f));
            a.z = 0.5f*a.z*(1.f + erff(a.z*0.70710678f));
            a.w = 0.5f*a.w*(1.f + erff(a.w*0.70710678f));
            *(float4*)&gsm[n*FH + p4] = a;
        }
    }
    __syncthreads();
    for (int i = tid; i < FH*TD; i += 256) wsm[i] = W2[i];
    __syncthreads();

    {   // r = t + gsm@W2 + c2 + tokens -> h2
        int jt = tid & 15, grp = tid >> 4;
        int j4 = jt*4;
        float4 c24 = *(const float4*)(c2 + j4);
        for (int n = grp; n < NT; n += 16) {
            float4 a = c24;
            for (int p = 0; p < FH; ++p) {
                float gv = gsm[n*FH + p];
                float4 w = *(float4*)&wsm[p*64 + j4];
                a.x = fmaf(gv, w.x, a.x); a.y = fmaf(gv, w.y, a.y);
                a.z = fmaf(gv, w.z, a.z); a.w = fmaf(gv, w.w, a.w);
            }
            float4 t4 = *(const float4*)(g_t + (size_t)b*NT*TD + n*TD + j4);
            float4 x4 = *(const float4*)(x   + (size_t)b*NT*TD + n*TD + j4);
            h2[n*65 + j4 + 0] = a.x + t4.x + x4.x;
            h2[n*65 + j4 + 1] = a.y + t4.y + x4.y;
            h2[n*65 + j4 + 2] = a.z + t4.z + x4.z;
            h2[n*65 + j4 + 3] = a.w + t4.w + x4.w;
        }
    }
    __syncthreads();

    if (tid < NT) {   // LN3
        float* r = &h2[tid*65];
        float mu = 0.f;
#pragma unroll
        for (int d = 0; d < 64; d++) mu += r[d];
        mu *= (1.f/64.f);
        float var = 0.f;
#pragma unroll
        for (int d = 0; d < 64; d++) { float t = r[d]-mu; var += t*t; }
        var *= (1.f/64.f);
        float inv = rsqrtf(var + 1e-5f);
#pragma unroll
        for (int d = 0; d < 64; d++)
            r[d] = (r[d]-mu)*inv*g3[d] + b3[d];
    }
    __syncthreads();

    if (tid < TD) {   // mean pool
        float s = 0.f;
        for (int n = 0; n < NT; ++n) s += h2[n*65 + tid];
        psm[tid] = s * (1.f/128.f);
    }
    __syncthreads();

    float val = 0.f;
    if (tid < 128) {  // head MLP
        float s = bf1[tid];
        for (int d = 0; d < TD; ++d)
            s = fmaf(psm[d], Wf1[d*128 + tid], s);
        s = fmaxf(s, 0.f);
        val = s * Wf2[tid];
    }
#pragma unroll
    for (int o = 16; o; o >>= 1)
        val += __shfl_xor_sync(0xffffffffu, val, o);
    if ((tid & 31) == 0) red[tid >> 5] = val;
    __syncthreads();
    if (tid == 0)
        out[b] = red[0] + red[1] + red[2] + red[3] + bf2[0];
}

// ---------------- launch ----------------
extern "C" void kernel_launch(void* const* d_in, const int* in_sizes, int n_in,
                              void* d_out, int out_size) {
    const float* x    = (const float*)d_in[0];
    const float* g1   = (const float*)d_in[1];
    const float* b1   = (const float*)d_in[2];
    const float* Wq   = (const float*)d_in[3];
    const float* bq   = (const float*)d_in[4];
    const float* Wk   = (const float*)d_in[5];
    const float* bk   = (const float*)d_in[6];
    const float* Wv   = (const float*)d_in[7];
    const float* bv   = (const float*)d_in[8];
    const float* Wo   = (const float*)d_in[9];
    const float* bo   = (const float*)d_in[10];
    const float* proj = (const float*)d_in[11];
    const float* g2   = (const float*)d_in[12];
    const float* b2   = (const float*)d_in[13];
    const float* W1   = (const float*)d_in[14];
    const float* c1   = (const float*)d_in[15];
    const float* W2   = (const float*)d_in[16];
    const float* c2   = (const float*)d_in[17];
    const float* g3   = (const float*)d_in[18];
    const float* b3   = (const float*)d_in[19];
    const float* Wf1  = (const float*)d_in[20];
    const float* bf1  = (const float*)d_in[21];
    const float* Wf2  = (const float*)d_in[22];
    const float* bf2  = (const float*)d_in[23];
    float* out = (float*)d_out;

    cudaFuncSetAttribute(k2_keys,    cudaFuncAttributeMaxDynamicSharedMemorySize, K2_SMEM);
    cudaFuncSetAttribute(k3_query,   cudaFuncAttributeMaxDynamicSharedMemorySize, K3_SMEM);
    cudaFuncSetAttribute(k4a_proj,   cudaFuncAttributeMaxDynamicSharedMemorySize, K4A_SMEM);
    cudaFuncSetAttribute(k4b_ff_head,cudaFuncAttributeMaxDynamicSharedMemorySize, K4B_SMEM);

    k_init<<<1, 1>>>();
    k1_ln_qkv<<<BB, 512>>>(x, g1, b1, Wq, bq, Wk, bk, Wv, bv);
    k2_keys<<<BB*HH, K2_THREADS, K2_SMEM>>>(proj);
    k3_query<<<BB*HH, 256 + 32, K3_SMEM>>>(proj);
    k4a_proj<<<BB, 256, K4A_SMEM>>>(x, Wo, bo);
    k4b_ff_head<<<BB, 256, K4B_SMEM>>>(x, g2, b2, W1, c1, W2, c2,
                                       g3, b3, Wf1, bf1, Wf2, bf2, out);
}